// round 10
// baseline (speedup 1.0000x reference)
#include <cuda_runtime.h>
#include <cuda_fp16.h>
#include <cstdint>

#define NN 100000
#define EE 1600000
#define DD 64
#define CHUNK 1024
#define NBLK ((NN + CHUNK - 1) / CHUNK)   // 98

// ---- scratch (device globals; no allocation allowed) ----
// g_cntflag: [0,NN) in-degree counts, [NN,NN+NBLK) scan flags. One memset.
__device__ int    g_cntflag[NN + NBLK];
__device__ int    g_agg[NBLK];
__device__ float  g_dis[NN];
__device__ int    g_rowptr[NN + 1];
__device__ int    g_cursor[NN];
__device__ int    g_csr[EE];           // src only (features pre-scaled by dis)
__device__ __half g_hA[NN * DD];
__device__ __half g_hB[NN * DD];

// ---------------- CSR build ----------------

// count in-degrees AND convert x -> fp16 (independent work, one kernel)
__global__ void k_countcvt(const int* __restrict__ ei, const float* __restrict__ x) {
    const int* dst = ei + EE;
    int i = blockIdx.x * blockDim.x + threadIdx.x;
    if (i < EE) atomicAdd(&g_cntflag[dst[i]], 1);
    if (i < NN * DD / 2) {
        float2 v = ((const float2*)x)[i];
        ((__half2*)g_hA)[i] = __float22half2_rn(v);
    }
}

// single-pass scan with decoupled lookback; afterwards scales hA row i by dis[i]
__global__ void k_scan() {
    __shared__ int s[CHUNK];
    __shared__ int exoff;
    volatile int* flag = (volatile int*)(g_cntflag + NN);
    int t = threadIdx.x, bid = blockIdx.x;
    int i = bid * CHUNK + t;
    int v = (i < NN) ? g_cntflag[i] : 0;
    s[t] = v;
    if (t == 0) exoff = 0;
    __syncthreads();
    for (int off = 1; off < CHUNK; off <<= 1) {
        int add = (t >= off) ? s[t - off] : 0;
        __syncthreads();
        s[t] += add;
        __syncthreads();
    }
    if (t == CHUNK - 1) {           // publish block aggregate
        g_agg[bid] = s[t];
        __threadfence();
        flag[bid] = 1;
    }
    if (t < bid) {                   // gather predecessors (≤97 spinners)
        while (flag[t] == 0) { }
        int a = *((volatile int*)&g_agg[t]);
        atomicAdd(&exoff, a);
    }
    __syncthreads();
    if (i < NN) {
        int rp = exoff + s[t] - v;   // global exclusive prefix
        g_rowptr[i] = rp;
        g_cursor[i] = rp;
        float dvv = rsqrtf((float)(v + 1));   // +1 self-loop
        g_dis[i] = dvv;
        // pre-scale input features: hA[i] *= dis[i]
        __half2 s2 = __half2half2(__float2half_rn(dvv));
        __half2* row = (__half2*)(g_hA + (size_t)i * DD);
#pragma unroll
        for (int u = 0; u < DD / 2; u++) row[u] = __hmul2(row[u], s2);
    }
    if (bid == 0 && t == 0) g_rowptr[NN] = EE;
}

// store src only (weight folded into pre-scaled features)
__global__ void k_fill(const int* __restrict__ ei) {
    const int* src = ei;
    const int* dst = ei + EE;
    int e = blockIdx.x * blockDim.x + threadIdx.x;
    if (e < EE) {
        int s = src[e], d = dst[e];
        int pos = atomicAdd(&g_cursor[d], 1);
        g_csr[pos] = s;
    }
}

// ---------------- fused layer ----------------
// xin holds h'[v] = dis[v]*h[v] (fp16). Aggregate: agg[v] = sum_e h'[src] + h'[v],
// acc = dv*agg, then Y = Acc @ W + b via tensor cores. OUT16 stores dis[row]*y
// (pre-scaled for the next layer); OUT32 stores raw y (final output).
// Gather: 16 lanes per row (int2 = 4 halves each), warp does 2 edges at once.

#define APAD 72   // fp16 row pitch (144B) -> ldmatrix bank-conflict-free

template <bool RELU, bool OUT16>
__global__ void __launch_bounds__(256) k_layer(
        const __half* __restrict__ xin, const float* __restrict__ W,
        const float* __restrict__ b, __half* __restrict__ out16,
        float* __restrict__ out32) {
    __shared__ __half sWh[64][APAD];   // W in fp16
    __shared__ __half sAh[32][APAD];   // per-block aggregates in fp16
    int t = threadIdx.x;

    // W fp32 -> fp16 into smem
    for (int i = t; i < 64 * 32; i += 256) {
        int k = i >> 5;
        int c = (i & 31) * 2;
        float2 w2 = *(const float2*)(W + k * 64 + c);
        *(__half2*)&sWh[k][c] = __float22half2_rn(w2);
    }

    int lane = t & 31;
    int wid  = t >> 5;
    int vblock = blockIdx.x * 32;             // 3125 blocks * 32 nodes
    int vbase  = vblock + wid * 4;

    const int2* __restrict__ xin22 = (const int2*)xin;  // 16 int2 per row

    // rowptr[vbase..vbase+4] + dis[vbase..vbase+3] in one warp load
    int   rpl = (lane < 5) ? g_rowptr[vbase + lane] : 0;
    float dvl = (lane < 4) ? g_dis[vbase + lane]    : 0.f;
    int rp[5];
#pragma unroll
    for (int q = 0; q < 5; q++) rp[q] = __shfl_sync(0xffffffffu, rpl, q);
    float dv[4];
#pragma unroll
    for (int n = 0; n < 4; n++) dv[n] = __shfl_sync(0xffffffffu, dvl, n);

    int eg  = lane >> 4;     // edge slot within pair (0..1)
    int ch2 = lane & 15;     // int2 index within row (0..15)

#pragma unroll
    for (int n = 0; n < 4; n++) {
        int v = vbase + n;
        float acc0 = 0.f, acc1 = 0.f, acc2 = 0.f, acc3 = 0.f;
        // self term h'[v] (group 0 only; group 1's copy arrives via reduction)
        if (eg == 0) {
            int2 sv = xin22[v * 16 + ch2];
            float2 a = __half22float2(*(__half2*)&sv.x);
            float2 c = __half22float2(*(__half2*)&sv.y);
            acc0 = a.x; acc1 = a.y; acc2 = c.x; acc3 = c.y;
        }
        int beg = rp[n], end = rp[n + 1];
        for (int j = beg; j < end; j += 32) {
            int cnt = min(32, end - j);
            int e = (lane < cnt) ? g_csr[j + lane] : 0;
#pragma unroll 4
            for (int k = 0; k < cnt; k += 2) {
                int s = __shfl_sync(0xffffffffu, e, k + eg);
                if (k + eg < cnt) {
                    int2 f = xin22[s * 16 + ch2];
                    float2 a = __half22float2(*(__half2*)&f.x);
                    float2 c = __half22float2(*(__half2*)&f.y);
                    acc0 += a.x; acc1 += a.y; acc2 += c.x; acc3 += c.y;
                }
            }
        }
        // combine the two edge-slot groups
        acc0 += __shfl_xor_sync(0xffffffffu, acc0, 16);
        acc1 += __shfl_xor_sync(0xffffffffu, acc1, 16);
        acc2 += __shfl_xor_sync(0xffffffffu, acc2, 16);
        acc3 += __shfl_xor_sync(0xffffffffu, acc3, 16);
        if (eg == 0) {     // lanes 0-15 hold the full sums
            float dvn = dv[n];
            float2 lo; lo.x = acc0 * dvn; lo.y = acc1 * dvn;
            float2 hi; hi.x = acc2 * dvn; hi.y = acc3 * dvn;
            __half2 h0 = __float22half2_rn(lo);
            __half2 h1 = __float22half2_rn(hi);
            int2 pk;
            pk.x = *(int*)&h0;
            pk.y = *(int*)&h1;
            *(int2*)&sAh[wid * 4 + n][ch2 * 4] = pk;
        }
    }
    __syncthreads();   // sWh + sAh ready

    // ---- tensor-core epilogue: warp w -> rows (w&1)*16..+15, cols (w>>1)*16..+15
    int mrow = (wid & 1) * 16;
    int ncol = (wid >> 1) * 16;

    float d0[4] = {0.f, 0.f, 0.f, 0.f};    // m16n8 tile at ncol
    float d1[4] = {0.f, 0.f, 0.f, 0.f};    // m16n8 tile at ncol+8

    int qa = lane >> 3;         // 0..3
    int ra = lane & 7;
#pragma unroll
    for (int ks = 0; ks < 4; ks++) {
        int arow = mrow + ra + (qa & 1) * 8;
        int acol = ks * 16 + (qa >> 1) * 8;
        uint32_t aaddr = (uint32_t)__cvta_generic_to_shared(&sAh[arow][acol]);
        uint32_t a0, a1, a2, a3;
        asm volatile("ldmatrix.sync.aligned.m8n8.x4.shared.b16 {%0,%1,%2,%3}, [%4];"
                     : "=r"(a0), "=r"(a1), "=r"(a2), "=r"(a3) : "r"(aaddr));

        int brow = ks * 16 + (lane & 15);      // lanes 0-15 used
        uint32_t baddr0 = (uint32_t)__cvta_generic_to_shared(&sWh[brow][ncol]);
        uint32_t baddr1 = (uint32_t)__cvta_generic_to_shared(&sWh[brow][ncol + 8]);
        uint32_t b0, b1, b2, b3;
        asm volatile("ldmatrix.sync.aligned.m8n8.x2.trans.shared.b16 {%0,%1}, [%2];"
                     : "=r"(b0), "=r"(b1) : "r"(baddr0));
        asm volatile("ldmatrix.sync.aligned.m8n8.x2.trans.shared.b16 {%0,%1}, [%2];"
                     : "=r"(b2), "=r"(b3) : "r"(baddr1));

        asm volatile("mma.sync.aligned.m16n8k16.row.col.f32.f16.f16.f32 "
                     "{%0,%1,%2,%3}, {%4,%5,%6,%7}, {%8,%9}, {%0,%1,%2,%3};"
                     : "+f"(d0[0]), "+f"(d0[1]), "+f"(d0[2]), "+f"(d0[3])
                     : "r"(a0), "r"(a1), "r"(a2), "r"(a3), "r"(b0), "r"(b1));
        asm volatile("mma.sync.aligned.m16n8k16.row.col.f32.f16.f16.f32 "
                     "{%0,%1,%2,%3}, {%4,%5,%6,%7}, {%8,%9}, {%0,%1,%2,%3};"
                     : "+f"(d1[0]), "+f"(d1[1]), "+f"(d1[2]), "+f"(d1[3])
                     : "r"(a0), "r"(a1), "r"(a2), "r"(a3), "r"(b2), "r"(b3));
    }

    // bias + relu (+ dis pre-scale for next layer) + store
    int drow = vblock + mrow + (lane >> 2);
    int dcol = ncol + (lane & 3) * 2;
    float2 bb0 = *(const float2*)(b + dcol);
    float2 bb1 = *(const float2*)(b + dcol + 8);
    float2 y00 = {d0[0] + bb0.x, d0[1] + bb0.y};   // row drow,   cols dcol
    float2 y01 = {d1[0] + bb1.x, d1[1] + bb1.y};   // row drow,   cols dcol+8
    float2 y10 = {d0[2] + bb0.x, d0[3] + bb0.y};   // row drow+8, cols dcol
    float2 y11 = {d1[2] + bb1.x, d1[3] + bb1.y};   // row drow+8, cols dcol+8
    if (RELU) {
        y00.x = fmaxf(y00.x, 0.f); y00.y = fmaxf(y00.y, 0.f);
        y01.x = fmaxf(y01.x, 0.f); y01.y = fmaxf(y01.y, 0.f);
        y10.x = fmaxf(y10.x, 0.f); y10.y = fmaxf(y10.y, 0.f);
        y11.x = fmaxf(y11.x, 0.f); y11.y = fmaxf(y11.y, 0.f);
    }
    if (OUT16) {
        float dd0 = g_dis[drow];
        float dd1 = g_dis[drow + 8];
        y00.x *= dd0; y00.y *= dd0; y01.x *= dd0; y01.y *= dd0;
        y10.x *= dd1; y10.y *= dd1; y11.x *= dd1; y11.y *= dd1;
        __half2* o2 = (__half2*)out16;
        o2[(size_t)drow * 32 + (dcol >> 1)]             = __float22half2_rn(y00);
        o2[(size_t)drow * 32 + ((dcol + 8) >> 1)]       = __float22half2_rn(y01);
        o2[(size_t)(drow + 8) * 32 + (dcol >> 1)]       = __float22half2_rn(y10);
        o2[(size_t)(drow + 8) * 32 + ((dcol + 8) >> 1)] = __float22half2_rn(y11);
    } else {
        *(float2*)(out32 + (size_t)drow * 64 + dcol)           = y00;
        *(float2*)(out32 + (size_t)drow * 64 + dcol + 8)       = y01;
        *(float2*)(out32 + (size_t)(drow + 8) * 64 + dcol)     = y10;
        *(float2*)(out32 + (size_t)(drow + 8) * 64 + dcol + 8) = y11;
    }
}

// ---------------- launch ----------------

extern "C" void kernel_launch(void* const* d_in, const int* in_sizes, int n_in,
                              void* d_out, int out_size) {
    const float* x  = (const float*)d_in[0];
    const int*   ei = (const int*)d_in[1];
    const float* W1 = (const float*)d_in[2];
    const float* b1 = (const float*)d_in[3];
    const float* W2 = (const float*)d_in[4];
    const float* b2 = (const float*)d_in[5];
    const float* W3 = (const float*)d_in[6];
    const float* b3 = (const float*)d_in[7];
    float* out = (float*)d_out;

    __half *hA, *hB;
    int *cntflag;
    cudaGetSymbolAddress((void**)&hA, g_hA);
    cudaGetSymbolAddress((void**)&hB, g_hB);
    cudaGetSymbolAddress((void**)&cntflag, g_cntflag);

    const int T = 256;
    cudaMemsetAsync(cntflag, 0, (NN + NBLK) * sizeof(int));
    {
        int work = NN * DD / 2;            // 3.2M > EE
        k_countcvt<<<(work + T - 1) / T, T>>>(ei, x);
    }
    k_scan<<<NBLK, CHUNK>>>();
    k_fill<<<(EE + T - 1) / T, T>>>(ei);

    const int LAYER_GRID = NN / 32;   // 3125 blocks, 32 nodes each

    k_layer<true,  true ><<<LAYER_GRID, T>>>(hA, W1, b1, hB, nullptr);
    k_layer<true,  true ><<<LAYER_GRID, T>>>(hB, W2, b2, hA, nullptr);
    k_layer<false, false><<<LAYER_GRID, T>>>(hA, W3, b3, nullptr, out);
}

// round 11
// speedup vs baseline: 1.2040x; 1.2040x over previous
#include <cuda_runtime.h>
#include <cuda_fp16.h>
#include <cstdint>

#define NN 100000
#define EE 1600000
#define DD 64
#define CHUNK 1024
#define NBLK ((NN + CHUNK - 1) / CHUNK)   // 98

// ---- scratch (device globals; no allocation allowed) ----
// g_cntflag: [0,NN) in-degree counts, [NN,NN+NBLK) scan flags. One memset.
__device__ int    g_cntflag[NN + NBLK];
__device__ int    g_agg[NBLK];
__device__ float  g_dis[NN];
__device__ int    g_rowptr[NN + 1];
__device__ int    g_cursor[NN];
__device__ int    g_csr[EE];           // src only (features pre-scaled by dis)
__device__ __half g_hA[NN * DD];
__device__ __half g_hB[NN * DD];

// ---------------- CSR build ----------------

// count in-degrees AND convert x -> fp16 (independent work, one kernel)
__global__ void k_countcvt(const int* __restrict__ ei, const float* __restrict__ x) {
    const int* dst = ei + EE;
    int i = blockIdx.x * blockDim.x + threadIdx.x;
    if (i < EE) atomicAdd(&g_cntflag[dst[i]], 1);
    if (i < NN * DD / 2) {
        float2 v = ((const float2*)x)[i];
        ((__half2*)g_hA)[i] = __float22half2_rn(v);
    }
}

// single-pass scan with decoupled lookback (all 98 blocks co-resident)
__global__ void k_scan() {
    __shared__ int s[CHUNK];
    __shared__ int exoff;
    volatile int* flag = (volatile int*)(g_cntflag + NN);
    int t = threadIdx.x, bid = blockIdx.x;
    int i = bid * CHUNK + t;
    int v = (i < NN) ? g_cntflag[i] : 0;
    s[t] = v;
    if (t == 0) exoff = 0;
    __syncthreads();
    for (int off = 1; off < CHUNK; off <<= 1) {
        int add = (t >= off) ? s[t - off] : 0;
        __syncthreads();
        s[t] += add;
        __syncthreads();
    }
    if (t == CHUNK - 1) {           // publish block aggregate
        g_agg[bid] = s[t];
        __threadfence();
        flag[bid] = 1;
    }
    if (t < bid) {                   // gather predecessors (≤97 spinners)
        while (flag[t] == 0) { }
        int a = *((volatile int*)&g_agg[t]);
        atomicAdd(&exoff, a);
    }
    __syncthreads();
    if (i < NN) {
        int rp = exoff + s[t] - v;   // global exclusive prefix
        g_rowptr[i] = rp;
        g_cursor[i] = rp;
        g_dis[i] = rsqrtf((float)(v + 1));   // +1 self-loop
    }
    if (bid == 0 && t == 0) g_rowptr[NN] = EE;
}

// CSR fill (src only) + COALESCED feature pre-scale: hA[i] *= dis[i/64].
// Element i>>5 maps 32 consecutive lanes to one row -> dis load is a warp
// broadcast, feature access is one 128B line per warp (no fragmentation).
__global__ void k_fillscale(const int* __restrict__ ei) {
    const int* src = ei;
    const int* dst = ei + EE;
    int i = blockIdx.x * blockDim.x + threadIdx.x;
    if (i < EE) {
        int s = src[i], d = dst[i];
        int pos = atomicAdd(&g_cursor[d], 1);
        g_csr[pos] = s;
    }
    if (i < NN * DD / 2) {
        __half2 s2 = __half2half2(__float2half_rn(g_dis[i >> 5]));
        __half2* p = (__half2*)g_hA;
        p[i] = __hmul2(p[i], s2);
    }
}

// ---------------- fused layer ----------------
// xin holds h'[v] = dis[v]*h[v] (fp16). Aggregate: agg[v] = sum_e h'[src] + h'[v],
// acc = dv*agg, then Y = Acc @ W + b via tensor cores. OUT16 stores dis[row]*y
// (pre-scaled for the next layer); OUT32 stores raw y (final output).
// Gather: 16 lanes per row (int2 = 4 halves each), warp does 2 edges at once.

#define APAD 72   // fp16 row pitch (144B) -> ldmatrix bank-conflict-free

template <bool RELU, bool OUT16>
__global__ void __launch_bounds__(256) k_layer(
        const __half* __restrict__ xin, const float* __restrict__ W,
        const float* __restrict__ b, __half* __restrict__ out16,
        float* __restrict__ out32) {
    __shared__ __half sWh[64][APAD];   // W in fp16
    __shared__ __half sAh[32][APAD];   // per-block aggregates in fp16
    int t = threadIdx.x;

    // W fp32 -> fp16 into smem
    for (int i = t; i < 64 * 32; i += 256) {
        int k = i >> 5;
        int c = (i & 31) * 2;
        float2 w2 = *(const float2*)(W + k * 64 + c);
        *(__half2*)&sWh[k][c] = __float22half2_rn(w2);
    }

    int lane = t & 31;
    int wid  = t >> 5;
    int vblock = blockIdx.x * 32;             // 3125 blocks * 32 nodes
    int vbase  = vblock + wid * 4;

    const int2* __restrict__ xin22 = (const int2*)xin;  // 16 int2 per row

    // rowptr[vbase..vbase+4] + dis[vbase..vbase+3] in one warp load
    int   rpl = (lane < 5) ? g_rowptr[vbase + lane] : 0;
    float dvl = (lane < 4) ? g_dis[vbase + lane]    : 0.f;
    int rp[5];
#pragma unroll
    for (int q = 0; q < 5; q++) rp[q] = __shfl_sync(0xffffffffu, rpl, q);
    float dv[4];
#pragma unroll
    for (int n = 0; n < 4; n++) dv[n] = __shfl_sync(0xffffffffu, dvl, n);

    int eg  = lane >> 4;     // edge slot within pair (0..1)
    int ch2 = lane & 15;     // int2 index within row (0..15)

#pragma unroll
    for (int n = 0; n < 4; n++) {
        int v = vbase + n;
        float acc0 = 0.f, acc1 = 0.f, acc2 = 0.f, acc3 = 0.f;
        // self term h'[v] (group 0 only; group 1's copy arrives via reduction)
        if (eg == 0) {
            int2 sv = xin22[v * 16 + ch2];
            float2 a = __half22float2(*(__half2*)&sv.x);
            float2 c = __half22float2(*(__half2*)&sv.y);
            acc0 = a.x; acc1 = a.y; acc2 = c.x; acc3 = c.y;
        }
        int beg = rp[n], end = rp[n + 1];
        for (int j = beg; j < end; j += 32) {
            int cnt = min(32, end - j);
            int e = (lane < cnt) ? g_csr[j + lane] : 0;
#pragma unroll 4
            for (int k = 0; k < cnt; k += 2) {
                int s = __shfl_sync(0xffffffffu, e, k + eg);
                if (k + eg < cnt) {
                    int2 f = xin22[s * 16 + ch2];
                    float2 a = __half22float2(*(__half2*)&f.x);
                    float2 c = __half22float2(*(__half2*)&f.y);
                    acc0 += a.x; acc1 += a.y; acc2 += c.x; acc3 += c.y;
                }
            }
        }
        // combine the two edge-slot groups
        acc0 += __shfl_xor_sync(0xffffffffu, acc0, 16);
        acc1 += __shfl_xor_sync(0xffffffffu, acc1, 16);
        acc2 += __shfl_xor_sync(0xffffffffu, acc2, 16);
        acc3 += __shfl_xor_sync(0xffffffffu, acc3, 16);
        if (eg == 0) {     // lanes 0-15 hold the full sums
            float dvn = dv[n];
            float2 lo; lo.x = acc0 * dvn; lo.y = acc1 * dvn;
            float2 hi; hi.x = acc2 * dvn; hi.y = acc3 * dvn;
            __half2 h0 = __float22half2_rn(lo);
            __half2 h1 = __float22half2_rn(hi);
            int2 pk;
            pk.x = *(int*)&h0;
            pk.y = *(int*)&h1;
            *(int2*)&sAh[wid * 4 + n][ch2 * 4] = pk;
        }
    }
    __syncthreads();   // sWh + sAh ready

    // ---- tensor-core epilogue: warp w -> rows (w&1)*16..+15, cols (w>>1)*16..+15
    int mrow = (wid & 1) * 16;
    int ncol = (wid >> 1) * 16;

    float d0[4] = {0.f, 0.f, 0.f, 0.f};    // m16n8 tile at ncol
    float d1[4] = {0.f, 0.f, 0.f, 0.f};    // m16n8 tile at ncol+8

    int qa = lane >> 3;         // 0..3
    int ra = lane & 7;
#pragma unroll
    for (int ks = 0; ks < 4; ks++) {
        int arow = mrow + ra + (qa & 1) * 8;
        int acol = ks * 16 + (qa >> 1) * 8;
        uint32_t aaddr = (uint32_t)__cvta_generic_to_shared(&sAh[arow][acol]);
        uint32_t a0, a1, a2, a3;
        asm volatile("ldmatrix.sync.aligned.m8n8.x4.shared.b16 {%0,%1,%2,%3}, [%4];"
                     : "=r"(a0), "=r"(a1), "=r"(a2), "=r"(a3) : "r"(aaddr));

        int brow = ks * 16 + (lane & 15);      // lanes 0-15 used
        uint32_t baddr0 = (uint32_t)__cvta_generic_to_shared(&sWh[brow][ncol]);
        uint32_t baddr1 = (uint32_t)__cvta_generic_to_shared(&sWh[brow][ncol + 8]);
        uint32_t b0, b1, b2, b3;
        asm volatile("ldmatrix.sync.aligned.m8n8.x2.trans.shared.b16 {%0,%1}, [%2];"
                     : "=r"(b0), "=r"(b1) : "r"(baddr0));
        asm volatile("ldmatrix.sync.aligned.m8n8.x2.trans.shared.b16 {%0,%1}, [%2];"
                     : "=r"(b2), "=r"(b3) : "r"(baddr1));

        asm volatile("mma.sync.aligned.m16n8k16.row.col.f32.f16.f16.f32 "
                     "{%0,%1,%2,%3}, {%4,%5,%6,%7}, {%8,%9}, {%0,%1,%2,%3};"
                     : "+f"(d0[0]), "+f"(d0[1]), "+f"(d0[2]), "+f"(d0[3])
                     : "r"(a0), "r"(a1), "r"(a2), "r"(a3), "r"(b0), "r"(b1));
        asm volatile("mma.sync.aligned.m16n8k16.row.col.f32.f16.f16.f32 "
                     "{%0,%1,%2,%3}, {%4,%5,%6,%7}, {%8,%9}, {%0,%1,%2,%3};"
                     : "+f"(d1[0]), "+f"(d1[1]), "+f"(d1[2]), "+f"(d1[3])
                     : "r"(a0), "r"(a1), "r"(a2), "r"(a3), "r"(b2), "r"(b3));
    }

    // bias + relu (+ dis pre-scale for next layer) + store
    int drow = vblock + mrow + (lane >> 2);
    int dcol = ncol + (lane & 3) * 2;
    float2 bb0 = *(const float2*)(b + dcol);
    float2 bb1 = *(const float2*)(b + dcol + 8);
    float2 y00 = {d0[0] + bb0.x, d0[1] + bb0.y};   // row drow,   cols dcol
    float2 y01 = {d1[0] + bb1.x, d1[1] + bb1.y};   // row drow,   cols dcol+8
    float2 y10 = {d0[2] + bb0.x, d0[3] + bb0.y};   // row drow+8, cols dcol
    float2 y11 = {d1[2] + bb1.x, d1[3] + bb1.y};   // row drow+8, cols dcol+8
    if (RELU) {
        y00.x = fmaxf(y00.x, 0.f); y00.y = fmaxf(y00.y, 0.f);
        y01.x = fmaxf(y01.x, 0.f); y01.y = fmaxf(y01.y, 0.f);
        y10.x = fmaxf(y10.x, 0.f); y10.y = fmaxf(y10.y, 0.f);
        y11.x = fmaxf(y11.x, 0.f); y11.y = fmaxf(y11.y, 0.f);
    }
    if (OUT16) {
        float dd0 = g_dis[drow];
        float dd1 = g_dis[drow + 8];
        y00.x *= dd0; y00.y *= dd0; y01.x *= dd0; y01.y *= dd0;
        y10.x *= dd1; y10.y *= dd1; y11.x *= dd1; y11.y *= dd1;
        __half2* o2 = (__half2*)out16;
        o2[(size_t)drow * 32 + (dcol >> 1)]             = __float22half2_rn(y00);
        o2[(size_t)drow * 32 + ((dcol + 8) >> 1)]       = __float22half2_rn(y01);
        o2[(size_t)(drow + 8) * 32 + (dcol >> 1)]       = __float22half2_rn(y10);
        o2[(size_t)(drow + 8) * 32 + ((dcol + 8) >> 1)] = __float22half2_rn(y11);
    } else {
        *(float2*)(out32 + (size_t)drow * 64 + dcol)           = y00;
        *(float2*)(out32 + (size_t)drow * 64 + dcol + 8)       = y01;
        *(float2*)(out32 + (size_t)(drow + 8) * 64 + dcol)     = y10;
        *(float2*)(out32 + (size_t)(drow + 8) * 64 + dcol + 8) = y11;
    }
}

// ---------------- launch ----------------

extern "C" void kernel_launch(void* const* d_in, const int* in_sizes, int n_in,
                              void* d_out, int out_size) {
    const float* x  = (const float*)d_in[0];
    const int*   ei = (const int*)d_in[1];
    const float* W1 = (const float*)d_in[2];
    const float* b1 = (const float*)d_in[3];
    const float* W2 = (const float*)d_in[4];
    const float* b2 = (const float*)d_in[5];
    const float* W3 = (const float*)d_in[6];
    const float* b3 = (const float*)d_in[7];
    float* out = (float*)d_out;

    __half *hA, *hB;
    int *cntflag;
    cudaGetSymbolAddress((void**)&hA, g_hA);
    cudaGetSymbolAddress((void**)&hB, g_hB);
    cudaGetSymbolAddress((void**)&cntflag, g_cntflag);

    const int T = 256;
    cudaMemsetAsync(cntflag, 0, (NN + NBLK) * sizeof(int));
    {
        int work = NN * DD / 2;            // 3.2M > EE
        k_countcvt<<<(work + T - 1) / T, T>>>(ei, x);
    }
    k_scan<<<NBLK, CHUNK>>>();
    {
        int work = NN * DD / 2;            // covers both fill (EE) and scale
        k_fillscale<<<(work + T - 1) / T, T>>>(ei);
    }

    const int LAYER_GRID = NN / 32;   // 3125 blocks, 32 nodes each

    k_layer<true,  true ><<<LAYER_GRID, T>>>(hA, W1, b1, hB, nullptr);
    k_layer<true,  true ><<<LAYER_GRID, T>>>(hB, W2, b2, hA, nullptr);
    k_layer<false, false><<<LAYER_GRID, T>>>(hA, W3, b3, nullptr, out);
}